// round 1
// baseline (speedup 1.0000x reference)
#include <cuda_runtime.h>
#include <cuda_bf16.h>
#include <math.h>

// -------------------------------------------------------------------------
// VectorizedConstantVelocityModel — GB300 sm_103a
//
// out = sum_events (b - ||zi(t)-zj(t)||^2)
//     - sum_{i<j} sqrt(pi)/(2 sqa) * exp(b + h^2 - c) * (erf(sqa*tn+h)-erf(sqa*t0+h))
// with a=||dv||^2 (clamped 1e-10), h=(dz.dv)/sqa, c=||dz||^2.
//
// Pair kernel: persistent blocks, balanced row-pairing (r, N-1-r), z/v tile
// packed float4 in 64KB dynamic shared. Per-block double partial -> global.
// Event kernel: grid-stride gather. Final 1-block reduction in double.
// -------------------------------------------------------------------------

#define PAIR_GRID    444      // 3 blocks/SM * 148 SMs (64KB smem -> 3 CTAs/SM)
#define PAIR_THREADS 256
#define EVT_GRID     128
#define EVT_THREADS  256
#define RED_THREADS  256

__device__ double g_pair_part[PAIR_GRID];
__device__ double g_evt_part[EVT_GRID];

__global__ __launch_bounds__(PAIR_THREADS)
void pair_kernel(const float* __restrict__ z0, const float* __restrict__ v0,
                 const float* __restrict__ t0p, const float* __restrict__ tnp,
                 const float* __restrict__ betap, int N)
{
    extern __shared__ float4 zv[];   // N entries: (zx, zy, vx, vy)
    const float t0 = t0p[0];
    const float tn = tnp[0];
    const float b  = betap[0];

    const int tid = threadIdx.x;
    for (int k = tid; k < N; k += blockDim.x) {
        zv[k] = make_float4(z0[2 * k], z0[2 * k + 1], v0[2 * k], v0[2 * k + 1]);
    }
    __syncthreads();

    float acc = 0.0f;
    const int half = (N + 1) >> 1;

    for (int r = blockIdx.x; r < half; r += gridDim.x) {
        const int r2 = N - 1 - r;
        #pragma unroll
        for (int rr = 0; rr < 2; rr++) {
            const int i = rr ? r2 : r;
            if (rr && r2 == r) break;
            const float4 a4 = zv[i];
            for (int j = i + 1 + tid; j < N; j += PAIR_THREADS) {
                const float4 b4 = zv[j];
                const float dzx = a4.x - b4.x;
                const float dzy = a4.y - b4.y;
                const float dvx = a4.z - b4.z;
                const float dvy = a4.w - b4.w;
                const float a   = fmaf(dvx, dvx, dvy * dvy);
                const float bbh = fmaf(dzx, dvx, dzy * dvy);   // dz.dv  (= bb/2)
                const float c   = fmaf(dzx, dzx, dzy * dzy);
                const float as  = fmaxf(a, 1e-10f);
                const float isq = rsqrtf(as);
                const float sqa = as * isq;                    // sqrt(a_safe)
                const float h   = bbh * isq;                   // bb/(2 sqa)
                const float ex  = __expf(fmaf(h, h, b - c));   // exp(b + h^2 - c)
                const float pref = 0.88622692545275801f * isq * ex; // sqrt(pi)/2 / sqa
                const float up  = erff(fmaf(sqa, tn, h));
                const float lo  = erff(fmaf(sqa, t0, h));
                acc += pref * (up - lo);
            }
        }
    }

    // block reduction in double
    __shared__ double red[PAIR_THREADS];
    red[tid] = (double)acc;
    __syncthreads();
    for (int s = PAIR_THREADS >> 1; s > 0; s >>= 1) {
        if (tid < s) red[tid] += red[tid + s];
        __syncthreads();
    }
    if (tid == 0) g_pair_part[blockIdx.x] = red[0];
}

__global__ __launch_bounds__(EVT_THREADS)
void evt_kernel(const float* __restrict__ data,
                const float* __restrict__ z0, const float* __restrict__ v0,
                const float* __restrict__ betap, int M)
{
    const float b = betap[0];
    float acc = 0.0f;
    for (int k = blockIdx.x * blockDim.x + threadIdx.x; k < M;
         k += gridDim.x * blockDim.x) {
        const float fi = data[3 * k + 0];
        const float fj = data[3 * k + 1];
        const float t  = data[3 * k + 2];
        const int i = (int)floorf(fi);
        const int j = (int)floorf(fj);
        const float zix = fmaf(v0[2 * i + 0], t, z0[2 * i + 0]);
        const float ziy = fmaf(v0[2 * i + 1], t, z0[2 * i + 1]);
        const float zjx = fmaf(v0[2 * j + 0], t, z0[2 * j + 0]);
        const float zjy = fmaf(v0[2 * j + 1], t, z0[2 * j + 1]);
        const float dx = zix - zjx;
        const float dy = ziy - zjy;
        acc += b - fmaf(dx, dx, dy * dy);
    }

    __shared__ double red[EVT_THREADS];
    const int tid = threadIdx.x;
    red[tid] = (double)acc;
    __syncthreads();
    for (int s = EVT_THREADS >> 1; s > 0; s >>= 1) {
        if (tid < s) red[tid] += red[tid + s];
        __syncthreads();
    }
    if (tid == 0) g_evt_part[blockIdx.x] = red[0];
}

__global__ __launch_bounds__(RED_THREADS)
void reduce_kernel(float* __restrict__ out)
{
    __shared__ double red[RED_THREADS];
    const int tid = threadIdx.x;
    double s = 0.0;
    for (int k = tid; k < PAIR_GRID; k += RED_THREADS) s -= g_pair_part[k];
    for (int k = tid; k < EVT_GRID; k += RED_THREADS)  s += g_evt_part[k];
    red[tid] = s;
    __syncthreads();
    for (int st = RED_THREADS >> 1; st > 0; st >>= 1) {
        if (tid < st) red[tid] += red[tid + st];
        __syncthreads();
    }
    if (tid == 0) out[0] = (float)red[0];
}

extern "C" void kernel_launch(void* const* d_in, const int* in_sizes, int n_in,
                              void* d_out, int out_size)
{
    // metadata order: data (M,3), t0, tn, beta (1,1), z0 (N,2), v0 (N,2)
    const float* data = (const float*)d_in[0];
    const float* t0   = (const float*)d_in[1];
    const float* tn   = (const float*)d_in[2];
    const float* beta = (const float*)d_in[3];
    const float* z0   = (const float*)d_in[4];
    const float* v0   = (const float*)d_in[5];

    const int M = in_sizes[0] / 3;
    const int N = in_sizes[4] / 2;

    const int smem = N * (int)sizeof(float4);   // 64 KB at N=4096
    static bool attr_set = false;
    if (!attr_set) {
        cudaFuncSetAttribute(pair_kernel,
                             cudaFuncAttributeMaxDynamicSharedMemorySize, smem);
        attr_set = true;
    }

    pair_kernel<<<PAIR_GRID, PAIR_THREADS, smem>>>(z0, v0, t0, tn, beta, N);
    evt_kernel<<<EVT_GRID, EVT_THREADS>>>(data, z0, v0, beta, M);
    reduce_kernel<<<1, RED_THREADS>>>((float*)d_out);
}

// round 2
// speedup vs baseline: 1.1528x; 1.1528x over previous
#include <cuda_runtime.h>
#include <cuda_bf16.h>
#include <math.h>

// -------------------------------------------------------------------------
// VectorizedConstantVelocityModel — GB300 sm_103a, round 2
//
// out = sum_events (b - ||zi(t)-zj(t)||^2)
//     - sum_{i<j} sqrt(pi)/(2 sqa) * exp(b + h^2 - c) * (erf(sqa*tn+h)-erf(sqa*t0+h))
//
// Changes vs R1 (39.4us):
//  * erff() -> Abramowitz-Stegun 7.1.26 fast erf (abs err ~1.5e-7, branchless,
//    saturates automatically for the large upper limit). ~13 instr vs ~25.
//  * 512-thread blocks, __launch_bounds__(512,3): occupancy 24 -> 48 warps/SM.
//  * warp-shuffle block reduction (less smem/sync).
// -------------------------------------------------------------------------

#define PAIR_GRID    444
#define PAIR_THREADS 512
#define EVT_GRID     128
#define EVT_THREADS  256
#define RED_THREADS  256

__device__ double g_pair_part[PAIR_GRID];
__device__ double g_evt_part[EVT_GRID];

// Abramowitz-Stegun 7.1.26: max abs error ~1.5e-7.
// erf(x) = sgn(x) * (1 - (a1 t + ... + a5 t^5) exp(-x^2)),  t = 1/(1 + p|x|)
__device__ __forceinline__ float fast_erf(float x)
{
    const float ax = fabsf(x);
    const float t  = __fdividef(1.0f, fmaf(0.3275911f, ax, 1.0f)); // MUFU.RCP
    float p = fmaf(1.061405429f, t, -1.453152027f);
    p = fmaf(p, t, 1.421413741f);
    p = fmaf(p, t, -0.284496736f);
    p = fmaf(p, t, 0.254829592f);
    p = p * t;
    const float ex = __expf(-ax * ax);          // flushes to 0 for |x| > ~9
    const float r  = fmaf(-p, ex, 1.0f);
    return copysignf(r, x);
}

__global__ __launch_bounds__(PAIR_THREADS, 3)
void pair_kernel(const float* __restrict__ z0, const float* __restrict__ v0,
                 const float* __restrict__ t0p, const float* __restrict__ tnp,
                 const float* __restrict__ betap, int N)
{
    extern __shared__ float4 zv[];   // N entries: (zx, zy, vx, vy)
    const float t0 = t0p[0];
    const float tn = tnp[0];
    const float b  = betap[0];

    const int tid = threadIdx.x;
    for (int k = tid; k < N; k += PAIR_THREADS) {
        zv[k] = make_float4(z0[2 * k], z0[2 * k + 1], v0[2 * k], v0[2 * k + 1]);
    }
    __syncthreads();

    float acc = 0.0f;
    const int half = (N + 1) >> 1;

    for (int r = blockIdx.x; r < half; r += gridDim.x) {
        const int r2 = N - 1 - r;
        #pragma unroll
        for (int rr = 0; rr < 2; rr++) {
            const int i = rr ? r2 : r;
            if (rr && r2 == r) break;
            const float4 a4 = zv[i];
            const float bc = b;   // exponent uses fmaf(h,h, b - c) below
            #pragma unroll 2
            for (int j = i + 1 + tid; j < N; j += PAIR_THREADS) {
                const float4 b4 = zv[j];
                const float dzx = a4.x - b4.x;
                const float dzy = a4.y - b4.y;
                const float dvx = a4.z - b4.z;
                const float dvy = a4.w - b4.w;
                const float a   = fmaf(dvx, dvx, dvy * dvy);
                const float bbh = fmaf(dzx, dvx, dzy * dvy);   // dz.dv (= bb/2)
                const float c   = fmaf(dzx, dzx, dzy * dzy);
                const float as  = fmaxf(a, 1e-10f);
                const float isq = rsqrtf(as);                  // MUFU.RSQ
                const float sqa = as * isq;                    // sqrt(a_safe)
                const float h   = bbh * isq;                   // bb/(2 sqa)
                const float ex  = __expf(fmaf(h, h, bc - c));  // exp(b + h^2 - c)
                const float pref = 0.88622692545275801f * isq * ex;
                const float up  = fast_erf(fmaf(sqa, tn, h));
                const float lo  = fast_erf(fmaf(sqa, t0, h));
                acc = fmaf(pref, up - lo, acc);
            }
        }
    }

    // warp-shuffle reduce, then per-warp doubles in smem
    #pragma unroll
    for (int off = 16; off > 0; off >>= 1)
        acc += __shfl_xor_sync(0xFFFFFFFFu, acc, off);

    __shared__ double wsum[PAIR_THREADS / 32];
    const int wid = tid >> 5, lid = tid & 31;
    if (lid == 0) wsum[wid] = (double)acc;
    __syncthreads();
    if (wid == 0) {
        double s = (lid < PAIR_THREADS / 32) ? wsum[lid] : 0.0;
        #pragma unroll
        for (int off = 8; off > 0; off >>= 1)
            s += __shfl_xor_sync(0xFFFFFFFFu, s, off);
        if (lid == 0) g_pair_part[blockIdx.x] = s;
    }
}

__global__ __launch_bounds__(EVT_THREADS)
void evt_kernel(const float* __restrict__ data,
                const float* __restrict__ z0, const float* __restrict__ v0,
                const float* __restrict__ betap, int M)
{
    const float b = betap[0];
    float acc = 0.0f;
    for (int k = blockIdx.x * blockDim.x + threadIdx.x; k < M;
         k += gridDim.x * blockDim.x) {
        const float fi = data[3 * k + 0];
        const float fj = data[3 * k + 1];
        const float t  = data[3 * k + 2];
        const int i = (int)floorf(fi);
        const int j = (int)floorf(fj);
        const float zix = fmaf(v0[2 * i + 0], t, z0[2 * i + 0]);
        const float ziy = fmaf(v0[2 * i + 1], t, z0[2 * i + 1]);
        const float zjx = fmaf(v0[2 * j + 0], t, z0[2 * j + 0]);
        const float zjy = fmaf(v0[2 * j + 1], t, z0[2 * j + 1]);
        const float dx = zix - zjx;
        const float dy = ziy - zjy;
        acc += b - fmaf(dx, dx, dy * dy);
    }

    #pragma unroll
    for (int off = 16; off > 0; off >>= 1)
        acc += __shfl_xor_sync(0xFFFFFFFFu, acc, off);

    __shared__ double wsum[EVT_THREADS / 32];
    const int tid = threadIdx.x;
    const int wid = tid >> 5, lid = tid & 31;
    if (lid == 0) wsum[wid] = (double)acc;
    __syncthreads();
    if (wid == 0) {
        double s = (lid < EVT_THREADS / 32) ? wsum[lid] : 0.0;
        #pragma unroll
        for (int off = 4; off > 0; off >>= 1)
            s += __shfl_xor_sync(0xFFFFFFFFu, s, off);
        if (lid == 0) g_evt_part[blockIdx.x] = s;
    }
}

__global__ __launch_bounds__(RED_THREADS)
void reduce_kernel(float* __restrict__ out)
{
    __shared__ double red[RED_THREADS];
    const int tid = threadIdx.x;
    double s = 0.0;
    for (int k = tid; k < PAIR_GRID; k += RED_THREADS) s -= g_pair_part[k];
    for (int k = tid; k < EVT_GRID; k += RED_THREADS)  s += g_evt_part[k];
    red[tid] = s;
    __syncthreads();
    for (int st = RED_THREADS >> 1; st > 0; st >>= 1) {
        if (tid < st) red[tid] += red[tid + st];
        __syncthreads();
    }
    if (tid == 0) out[0] = (float)red[0];
}

extern "C" void kernel_launch(void* const* d_in, const int* in_sizes, int n_in,
                              void* d_out, int out_size)
{
    // metadata order: data (M,3), t0, tn, beta (1,1), z0 (N,2), v0 (N,2)
    const float* data = (const float*)d_in[0];
    const float* t0   = (const float*)d_in[1];
    const float* tn   = (const float*)d_in[2];
    const float* beta = (const float*)d_in[3];
    const float* z0   = (const float*)d_in[4];
    const float* v0   = (const float*)d_in[5];

    const int M = in_sizes[0] / 3;
    const int N = in_sizes[4] / 2;

    const int smem = N * (int)sizeof(float4);   // 64 KB at N=4096
    static bool attr_set = false;
    if (!attr_set) {
        cudaFuncSetAttribute(pair_kernel,
                             cudaFuncAttributeMaxDynamicSharedMemorySize, smem);
        attr_set = true;
    }

    pair_kernel<<<PAIR_GRID, PAIR_THREADS, smem>>>(z0, v0, t0, tn, beta, N);
    evt_kernel<<<EVT_GRID, EVT_THREADS>>>(data, z0, v0, beta, M);
    reduce_kernel<<<1, RED_THREADS>>>((float*)d_out);
}